// round 2
// baseline (speedup 1.0000x reference)
#include <cuda_runtime.h>
#include <cstdint>

// ---------------------------------------------------------------------------
// SparseConvNet_Triplane: masked 3D CNN (64^3 -> 32^3 -> 16^3) + triplane
// projection + bilinear point sampling.  Pure fp32 baseline.
// ---------------------------------------------------------------------------

#define NV0 (64*64*64)      // 262144
#define NV1 (32*32*32)      // 32768
#define NV2 (16*16*16)      // 4096

// Scratch (device globals; no runtime allocation allowed).
__device__ float g_m0[NV0];
__device__ float g_m1[NV1];
__device__ float g_m2[NV2];
__device__ float g_xm[16 * NV0];        // masked input
__device__ float g_bufA[32 * NV0];      // ping
__device__ float g_bufB[32 * NV0];      // pong
__device__ float g_planes[3 * 16 * 16 * 128];   // [plane][y][x][c]
__device__ int   g_mask_mode;           // 0=byte, 1=int32, 2=float32

// ---------------------------------------------------------------------------
// Detect how the bool mask is stored: 1-byte, int32, or float32.
// Scans NV0/4 words (valid under every interpretation).
// ---------------------------------------------------------------------------
__global__ void detect_mask_kernel(const unsigned int* __restrict__ mw)
{
    __shared__ int s_int, s_flt;
    if (threadIdx.x == 0) { s_int = 1; s_flt = 1; }
    __syncthreads();
    for (int i = threadIdx.x; i < NV0 / 4; i += 256) {
        unsigned int w = mw[i];
        if (w != 0u && w != 1u)           s_int = 0;   // benign race: all write 0
        if (w != 0u && w != 0x3F800000u)  s_flt = 0;
    }
    __syncthreads();
    if (threadIdx.x == 0)
        g_mask_mode = s_int ? 1 : (s_flt ? 2 : 0);
}

// ---------------------------------------------------------------------------
// Prep: mask -> float, x * mask
// ---------------------------------------------------------------------------
__global__ void prep_kernel(const void* __restrict__ mb,
                            const float* __restrict__ x)
{
    int v = blockIdx.x * 256 + threadIdx.x;
    int mode = g_mask_mode;
    float m;
    if (mode == 1)      m = ((const int*)mb)[v]            ? 1.0f : 0.0f;
    else if (mode == 2) m = (((const float*)mb)[v] != 0.f) ? 1.0f : 0.0f;
    else                m = ((const unsigned char*)mb)[v]  ? 1.0f : 0.0f;
    g_m0[v] = m;
#pragma unroll
    for (int c = 0; c < 16; c++)
        g_xm[c * NV0 + v] = x[c * NV0 + v] * m;
}

// 3x3x3 max-pool stride 2 pad 1 on the float mask.
__global__ void downmask_kernel(const float* __restrict__ mi,
                                float* __restrict__ mo, int Din)
{
    int Dout = Din >> 1;
    int v = blockIdx.x * blockDim.x + threadIdx.x;
    int wI = v % Dout;
    int t  = v / Dout;
    int hI = t % Dout;
    int dI = t / Dout;
    float s = 0.0f;
#pragma unroll
    for (int kd = 0; kd < 3; kd++) {
        int id = 2 * dI + kd - 1;
        if ((unsigned)id >= (unsigned)Din) continue;
#pragma unroll
        for (int kh = 0; kh < 3; kh++) {
            int ih = 2 * hI + kh - 1;
            if ((unsigned)ih >= (unsigned)Din) continue;
#pragma unroll
            for (int kw = 0; kw < 3; kw++) {
                int iw = 2 * wI + kw - 1;
                if ((unsigned)iw >= (unsigned)Din) continue;
                s = fmaxf(s, mi[(id * Din + ih) * Din + iw]);
            }
        }
    }
    mo[v] = s;
}

// ---------------------------------------------------------------------------
// Direct 3x3x3 conv + BN + ReLU + mask.
// One thread = one output voxel, 32 output channels in registers.
// Weights staged in smem in Cin-chunks of 8.
// Grid: (nOutVox/256, CO/32).  nOutVox is always a multiple of 256 here.
// ---------------------------------------------------------------------------
__global__ void conv_bn_relu_mask(
    const float* __restrict__ in, float* __restrict__ out,
    const float* __restrict__ w, const float* __restrict__ bn,
    const float* __restrict__ mask,
    int CI, int CO, int Din, int Dout, int stride)
{
    __shared__ float ws[8 * 27 * 32];   // 27648 B

    const int vox    = blockIdx.x * 256 + threadIdx.x;
    const int coBase = blockIdx.y * 32;
    const int nOut   = Dout * Dout * Dout;
    const int vol    = Din * Din * Din;

    const int wI = vox % Dout;
    const int t0 = vox / Dout;
    const int hI = t0 % Dout;
    const int dI = t0 / Dout;

    // Precompute the 27 tap offsets (or -1 if out of bounds).
    int offs[27];
    {
        int q = 0;
#pragma unroll
        for (int kd = 0; kd < 3; kd++) {
            int id = dI * stride + kd - 1;
            bool vd = (unsigned)id < (unsigned)Din;
#pragma unroll
            for (int kh = 0; kh < 3; kh++) {
                int ih = hI * stride + kh - 1;
                bool vh = vd && ((unsigned)ih < (unsigned)Din);
#pragma unroll
                for (int kw = 0; kw < 3; kw++) {
                    int iw = wI * stride + kw - 1;
                    bool vv = vh && ((unsigned)iw < (unsigned)Din);
                    offs[q++] = vv ? ((id * Din + ih) * Din + iw) : -1;
                }
            }
        }
    }

    float acc[32];
#pragma unroll
    for (int i = 0; i < 32; i++) acc[i] = 0.0f;

    for (int c0 = 0; c0 < CI; c0 += 8) {
        __syncthreads();
        // stage 8 x 27 x 32 weights:  ws[((cl*27)+k)*32+co]
        for (int i = threadIdx.x; i < 8 * 27 * 32; i += 256) {
            int co = i & 31;
            int r  = i >> 5;
            int k  = r % 27;
            int cl = r / 27;
            ws[i] = w[((size_t)(coBase + co) * CI + (c0 + cl)) * 27 + k];
        }
        __syncthreads();

#pragma unroll 1
        for (int cl = 0; cl < 8; cl++) {
            const float* ip = in + (size_t)(c0 + cl) * vol;
            const float* wp = ws + cl * (27 * 32);
#pragma unroll
            for (int k = 0; k < 27; k++) {
                int o = offs[k];
                float v = (o >= 0) ? __ldg(ip + o) : 0.0f;
#pragma unroll
                for (int co = 0; co < 32; co++)
                    acc[co] = fmaf(wp[k * 32 + co], v, acc[co]);
            }
        }
    }

    const float m = mask[vox];
#pragma unroll
    for (int co = 0; co < 32; co++) {
        int cg   = coBase + co;
        float g  = __ldg(bn + cg);
        float b  = __ldg(bn + CO + cg);
        float mu = __ldg(bn + 2 * CO + cg);
        float vv = __ldg(bn + 3 * CO + cg);
        float s  = g * rsqrtf(vv + 1e-3f);
        float y  = fmaf(s, acc[co] - mu, b);
        out[(size_t)cg * nOut + vox] = fmaxf(y, 0.0f) * m;
    }
}

// ---------------------------------------------------------------------------
// Triplane projection: x [128][16][16][16] -> planes [3][16][16][128]
//   plane 0 (xy): mean over d, rows=h cols=w
//   plane 1 (yz): mean over w, rows=d cols=h
//   plane 2 (xz): mean over h, rows=d cols=w
// ---------------------------------------------------------------------------
__global__ void proj_kernel(const float* __restrict__ x)
{
    int idx = blockIdx.x * 128 + threadIdx.x;   // 3*16*16*128 = 98304
    int c = idx & 127;
    int r = idx >> 7;
    int b = r & 15;  r >>= 4;
    int a = r & 15;
    int p = r >> 4;

    float s = 0.0f;
    if (p == 0) {
#pragma unroll
        for (int d = 0; d < 16; d++) s += x[((c * 16 + d) * 16 + a) * 16 + b];
    } else if (p == 1) {
#pragma unroll
        for (int q = 0; q < 16; q++) s += x[((c * 16 + a) * 16 + b) * 16 + q];
    } else {
#pragma unroll
        for (int q = 0; q < 16; q++) s += x[((c * 16 + a) * 16 + q) * 16 + b];
    }
    g_planes[idx] = s * (1.0f / 16.0f);
}

// ---------------------------------------------------------------------------
// Point sampling: 1 block = 1 point, 128 threads = channels.
// planes layout [plane][y][x][c] -> coalesced tap loads.
// ---------------------------------------------------------------------------
__device__ __forceinline__ float bil_tap(const float* __restrict__ img,
                                         float gx, float gy, int c)
{
    float ix = (gx + 1.0f) * 0.5f * 15.0f;
    float iy = (gy + 1.0f) * 0.5f * 15.0f;
    float x0f = floorf(ix), y0f = floorf(iy);
    int   x0  = (int)x0f,   y0  = (int)y0f;
    float wx = ix - x0f, wy = iy - y0f;

    float acc = 0.0f;
#pragma unroll
    for (int j = 0; j < 2; j++) {
#pragma unroll
        for (int i = 0; i < 2; i++) {
            int xx = x0 + i, yy = y0 + j;
            float w = (j ? wy : 1.0f - wy) * (i ? wx : 1.0f - wx);
            bool valid = (unsigned)xx < 16u && (unsigned)yy < 16u;
            int xc = min(max(xx, 0), 15);
            int yc = min(max(yy, 0), 15);
            float v = img[(yc * 16 + xc) * 128 + c];
            acc += v * (valid ? w : 0.0f);
        }
    }
    return acc;
}

__global__ void sample_kernel(const float* __restrict__ coords,
                              float* __restrict__ out)
{
    const int p = blockIdx.x;
    const int c = threadIdx.x;
    const float cx = coords[p * 3 + 0];
    const float cy = coords[p * 3 + 1];
    const float cz = coords[p * 3 + 2];

    const int psz = 16 * 16 * 128;
    float acc = 0.0f;
    acc += bil_tap(g_planes + 0 * psz, cx, cy, c);   // p_xy: ix<-x, iy<-y
    acc += bil_tap(g_planes + 1 * psz, cy, cz, c);   // p_yz: ix<-y, iy<-z
    acc += bil_tap(g_planes + 2 * psz, cx, cz, c);   // p_xz: ix<-x, iy<-z

    out[p * 128 + c] = acc;
}

// ---------------------------------------------------------------------------
// Launch
// ---------------------------------------------------------------------------
extern "C" void kernel_launch(void* const* d_in, const int* in_sizes, int n_in,
                              void* d_out, int out_size)
{
    const float*         x      = (const float*)d_in[0];
    const void*          mask   = d_in[1];
    const float*         coords = (const float*)d_in[2];
    const float* w0a = (const float*)d_in[3];  const float* bn0a = (const float*)d_in[4];
    const float* w0b = (const float*)d_in[5];  const float* bn0b = (const float*)d_in[6];
    const float* wd0 = (const float*)d_in[7];  const float* bnd0 = (const float*)d_in[8];
    const float* w1a = (const float*)d_in[9];  const float* bn1a = (const float*)d_in[10];
    const float* w1b = (const float*)d_in[11]; const float* bn1b = (const float*)d_in[12];
    const float* wd1 = (const float*)d_in[13]; const float* bnd1 = (const float*)d_in[14];
    const float* w2a = (const float*)d_in[15]; const float* bn2a = (const float*)d_in[16];
    const float* w2b = (const float*)d_in[17]; const float* bn2b = (const float*)d_in[18];
    const float* w2c = (const float*)d_in[19]; const float* bn2c = (const float*)d_in[20];

    float *m0, *m1, *m2, *xm, *A, *B;
    cudaGetSymbolAddress((void**)&m0, g_m0);
    cudaGetSymbolAddress((void**)&m1, g_m1);
    cudaGetSymbolAddress((void**)&m2, g_m2);
    cudaGetSymbolAddress((void**)&xm, g_xm);
    cudaGetSymbolAddress((void**)&A,  g_bufA);
    cudaGetSymbolAddress((void**)&B,  g_bufB);

    // mask dtype detection + pyramid + masked input
    detect_mask_kernel<<<1, 256>>>((const unsigned int*)mask);
    prep_kernel<<<NV0 / 256, 256>>>(mask, x);
    downmask_kernel<<<NV1 / 256, 256>>>(m0, m1, 64);
    downmask_kernel<<<NV2 / 256, 256>>>(m1, m2, 32);

    // level 0 (64^3)
    conv_bn_relu_mask<<<dim3(NV0 / 256, 1), 256>>>(xm, A, w0a, bn0a, m0, 16, 32, 64, 64, 1);
    conv_bn_relu_mask<<<dim3(NV0 / 256, 1), 256>>>(A,  B, w0b, bn0b, m0, 32, 32, 64, 64, 1);
    // downsample to 32^3
    conv_bn_relu_mask<<<dim3(NV1 / 256, 1), 256>>>(B,  A, wd0, bnd0, m1, 32, 32, 64, 32, 2);
    // level 1 (32^3)
    conv_bn_relu_mask<<<dim3(NV1 / 256, 2), 256>>>(A,  B, w1a, bn1a, m1, 32, 64, 32, 32, 1);
    conv_bn_relu_mask<<<dim3(NV1 / 256, 2), 256>>>(B,  A, w1b, bn1b, m1, 64, 64, 32, 32, 1);
    // downsample to 16^3
    conv_bn_relu_mask<<<dim3(NV2 / 256, 4), 256>>>(A,  B, wd1, bnd1, m2, 64, 128, 32, 16, 2);
    // level 2 (16^3)
    conv_bn_relu_mask<<<dim3(NV2 / 256, 4), 256>>>(B,  A, w2a, bn2a, m2, 128, 128, 16, 16, 1);
    conv_bn_relu_mask<<<dim3(NV2 / 256, 4), 256>>>(A,  B, w2b, bn2b, m2, 128, 128, 16, 16, 1);
    conv_bn_relu_mask<<<dim3(NV2 / 256, 4), 256>>>(B,  A, w2c, bn2c, m2, 128, 128, 16, 16, 1);

    // projections + sampling
    proj_kernel<<<(3 * 16 * 16 * 128) / 128, 128>>>(A);
    int P = in_sizes[2] / 3;
    sample_kernel<<<P, 128>>>(coords, (float*)d_out);
}

// round 3
// speedup vs baseline: 1.2554x; 1.2554x over previous
#include <cuda_runtime.h>
#include <cstdint>

// ---------------------------------------------------------------------------
// SparseConvNet_Triplane: masked 3D CNN (64^3 -> 32^3 -> 16^3) + triplane
// projection + bilinear point sampling.
// R3: packed fp32x2 FMA conv, 2 voxels/thread, per-layer CO tiling.
// ---------------------------------------------------------------------------

#define NV0 (64*64*64)      // 262144
#define NV1 (32*32*32)      // 32768
#define NV2 (16*16*16)      // 4096

// Scratch (device globals; no runtime allocation allowed).
__device__ float g_m0[NV0];
__device__ float g_m1[NV1];
__device__ float g_m2[NV2];
__device__ float g_xm[16 * NV0];        // masked input
__device__ float g_bufA[32 * NV0];      // ping
__device__ float g_bufB[32 * NV0];      // pong
__device__ float g_planes[3 * 16 * 16 * 128];   // [plane][y][x][c]
__device__ int   g_mask_mode;           // 0=byte, 1=int32, 2=float32

// ---------------------------------------------------------------------------
// f32x2 packed helpers
// ---------------------------------------------------------------------------
__device__ __forceinline__ unsigned long long ffma2(unsigned long long a,
                                                    unsigned long long b,
                                                    unsigned long long c)
{
    unsigned long long d;
    asm("fma.rn.f32x2 %0, %1, %2, %3;" : "=l"(d) : "l"(a), "l"(b), "l"(c));
    return d;
}
__device__ __forceinline__ unsigned long long bcast2(float v)
{
    unsigned long long d;
    asm("mov.b64 %0, {%1, %1};" : "=l"(d) : "f"(v));
    return d;
}
__device__ __forceinline__ float2 unpack2(unsigned long long a)
{
    float2 r;
    asm("mov.b64 {%0, %1}, %2;" : "=f"(r.x), "=f"(r.y) : "l"(a));
    return r;
}

// ---------------------------------------------------------------------------
// Detect how the bool mask is stored: 1-byte, int32, or float32.
// ---------------------------------------------------------------------------
__global__ void detect_mask_kernel(const unsigned int* __restrict__ mw)
{
    __shared__ int s_int, s_flt;
    if (threadIdx.x == 0) { s_int = 1; s_flt = 1; }
    __syncthreads();
    for (int i = threadIdx.x; i < NV0 / 4; i += 256) {
        unsigned int w = mw[i];
        if (w != 0u && w != 1u)           s_int = 0;   // benign race: all write 0
        if (w != 0u && w != 0x3F800000u)  s_flt = 0;
    }
    __syncthreads();
    if (threadIdx.x == 0)
        g_mask_mode = s_int ? 1 : (s_flt ? 2 : 0);
}

// ---------------------------------------------------------------------------
// Prep: mask -> float, x * mask
// ---------------------------------------------------------------------------
__global__ void prep_kernel(const void* __restrict__ mb,
                            const float* __restrict__ x)
{
    int v = blockIdx.x * 256 + threadIdx.x;
    int mode = g_mask_mode;
    float m;
    if (mode == 1)      m = ((const int*)mb)[v]            ? 1.0f : 0.0f;
    else if (mode == 2) m = (((const float*)mb)[v] != 0.f) ? 1.0f : 0.0f;
    else                m = ((const unsigned char*)mb)[v]  ? 1.0f : 0.0f;
    g_m0[v] = m;
#pragma unroll
    for (int c = 0; c < 16; c++)
        g_xm[c * NV0 + v] = x[c * NV0 + v] * m;
}

// 3x3x3 max-pool stride 2 pad 1 on the float mask.
__global__ void downmask_kernel(const float* __restrict__ mi,
                                float* __restrict__ mo, int Din)
{
    int Dout = Din >> 1;
    int v = blockIdx.x * blockDim.x + threadIdx.x;
    int wI = v % Dout;
    int t  = v / Dout;
    int hI = t % Dout;
    int dI = t / Dout;
    float s = 0.0f;
#pragma unroll
    for (int kd = 0; kd < 3; kd++) {
        int id = 2 * dI + kd - 1;
        if ((unsigned)id >= (unsigned)Din) continue;
#pragma unroll
        for (int kh = 0; kh < 3; kh++) {
            int ih = 2 * hI + kh - 1;
            if ((unsigned)ih >= (unsigned)Din) continue;
#pragma unroll
            for (int kw = 0; kw < 3; kw++) {
                int iw = 2 * wI + kw - 1;
                if ((unsigned)iw >= (unsigned)Din) continue;
                s = fmaxf(s, mi[(id * Din + ih) * Din + iw]);
            }
        }
    }
    mo[v] = s;
}

// ---------------------------------------------------------------------------
// Direct 3x3x3 conv + BN + ReLU + mask, f32x2 packed.
// One thread = TWO output voxels (adjacent in W), CO_T output channels held
// as CO_T/2 x 2 packed f32x2 accumulators.  Weights staged in smem in
// Cin-chunks of 8, read as 64-bit channel-pairs (broadcast LDS.64).
// Per row of taps: 1 scalar + 1-2 float2 input loads feed both voxels.
// Grid: (nOutVox/512, CO/CO_T), 256 threads.
// ---------------------------------------------------------------------------
template<int CO_T, int S>
__global__ void conv2_kernel(
    const float* __restrict__ in, float* __restrict__ out,
    const float* __restrict__ w, const float* __restrict__ bn,
    const float* __restrict__ mask,
    int CI, int CO, int Din, int Dout)
{
    constexpr int HP   = CO_T / 2;   // channel pairs
    constexpr int NVAL = S + 3;      // input cols touched per row by the voxel pair

    __shared__ __align__(16) float ws[8 * 27 * CO_T];
    const unsigned long long* ws64 = (const unsigned long long*)ws;

    const int vox0   = (blockIdx.x * 256 + threadIdx.x) * 2;
    const int coBase = blockIdx.y * CO_T;
    const int nOut   = Dout * Dout * Dout;
    const int vol    = Din * Din * Din;

    const int w0 = vox0 % Dout;                 // even
    int t        = vox0 / Dout;
    const int hI = t % Dout;
    const int dI = t / Dout;

    // 9 (kd,kh) row base offsets at column S*w0 (or -1 if row out of bounds).
    int rowOff[9];
    {
        int q = 0;
#pragma unroll
        for (int kd = 0; kd < 3; kd++) {
            int id = dI * S + kd - 1;
            bool vd = (unsigned)id < (unsigned)Din;
#pragma unroll
            for (int kh = 0; kh < 3; kh++) {
                int ih = hI * S + kh - 1;
                bool ok = vd && ((unsigned)ih < (unsigned)Din);
                rowOff[q++] = ok ? ((id * Din + ih) * Din + w0 * S) : -1;
            }
        }
    }
    const bool leftOk  = (w0 > 0);
    const bool rightOk = (S == 2) ? true : (w0 + 2 < Din);

    unsigned long long acc[HP][2];
#pragma unroll
    for (int p = 0; p < HP; p++) { acc[p][0] = 0ull; acc[p][1] = 0ull; }

    for (int c0 = 0; c0 < CI; c0 += 8) {
        __syncthreads();
        // stage 8 x 27 x CO_T weights:  ws[((cl*27)+k)*CO_T + co]
        for (int i = threadIdx.x; i < 8 * 27 * CO_T; i += 256) {
            int co = i % CO_T;
            int r  = i / CO_T;
            int k  = r % 27;
            int cl = r / 27;
            ws[i] = w[((size_t)(coBase + co) * CI + (c0 + cl)) * 27 + k];
        }
        __syncthreads();

#pragma unroll 1
        for (int cl = 0; cl < 8; cl++) {
            const float* ip = in + (size_t)(c0 + cl) * vol;
            const unsigned long long* wp = ws64 + cl * (27 * HP);

#pragma unroll
            for (int r = 0; r < 9; r++) {
                const int  ro = rowOff[r];
                const bool rv = (ro >= 0);

                float v[NVAL];
                v[0] = (rv && leftOk) ? __ldg(ip + ro - 1) : 0.0f;
                if (rv) {
                    float2 a = *(const float2*)(ip + ro);
                    v[1] = a.x; v[2] = a.y;
                } else { v[1] = 0.0f; v[2] = 0.0f; }
                if (S == 1) {
                    v[3] = (rv && rightOk) ? __ldg(ip + ro + 2) : 0.0f;
                } else {
                    if (rv) {
                        float2 b = *(const float2*)(ip + ro + 2);
                        v[3] = b.x; v[NVAL - 1] = b.y;
                    } else { v[3] = 0.0f; v[NVAL - 1] = 0.0f; }
                }

                unsigned long long pv[NVAL];
#pragma unroll
                for (int i2 = 0; i2 < NVAL; i2++) pv[i2] = bcast2(v[i2]);

#pragma unroll
                for (int kw = 0; kw < 3; kw++) {
                    const unsigned long long* wk = wp + (r * 3 + kw) * HP;
#pragma unroll
                    for (int p = 0; p < HP; p++) {
                        unsigned long long wpair = wk[p];
                        acc[p][0] = ffma2(wpair, pv[kw],     acc[p][0]);
                        acc[p][1] = ffma2(wpair, pv[kw + S], acc[p][1]);
                    }
                }
            }
        }
    }

    const float mv0 = mask[vox0];
    const float mv1 = mask[vox0 + 1];
#pragma unroll
    for (int p = 0; p < HP; p++) {
        float2 a0 = unpack2(acc[p][0]);   // (co0,co1) @ vox0
        float2 a1 = unpack2(acc[p][1]);   // (co0,co1) @ vox1
        int cg0 = coBase + 2 * p;
        int cg1 = cg0 + 1;

        float g0  = __ldg(bn + cg0),         g1  = __ldg(bn + cg1);
        float b0  = __ldg(bn + CO + cg0),    b1  = __ldg(bn + CO + cg1);
        float u0  = __ldg(bn + 2*CO + cg0),  u1  = __ldg(bn + 2*CO + cg1);
        float vv0 = __ldg(bn + 3*CO + cg0),  vv1 = __ldg(bn + 3*CO + cg1);
        float s0 = g0 * rsqrtf(vv0 + 1e-3f);
        float s1 = g1 * rsqrtf(vv1 + 1e-3f);

        float2 o0, o1;
        o0.x = fmaxf(fmaf(s0, a0.x - u0, b0), 0.0f) * mv0;
        o0.y = fmaxf(fmaf(s0, a1.x - u0, b0), 0.0f) * mv1;
        o1.x = fmaxf(fmaf(s1, a0.y - u1, b1), 0.0f) * mv0;
        o1.y = fmaxf(fmaf(s1, a1.y - u1, b1), 0.0f) * mv1;

        *(float2*)(out + (size_t)cg0 * nOut + vox0) = o0;
        *(float2*)(out + (size_t)cg1 * nOut + vox0) = o1;
    }
}

// ---------------------------------------------------------------------------
// Triplane projection: x [128][16][16][16] -> planes [3][16][16][128]
// ---------------------------------------------------------------------------
__global__ void proj_kernel(const float* __restrict__ x)
{
    int idx = blockIdx.x * 128 + threadIdx.x;   // 3*16*16*128 = 98304
    int c = idx & 127;
    int r = idx >> 7;
    int b = r & 15;  r >>= 4;
    int a = r & 15;
    int p = r >> 4;

    float s = 0.0f;
    if (p == 0) {
#pragma unroll
        for (int d = 0; d < 16; d++) s += x[((c * 16 + d) * 16 + a) * 16 + b];
    } else if (p == 1) {
#pragma unroll
        for (int q = 0; q < 16; q++) s += x[((c * 16 + a) * 16 + b) * 16 + q];
    } else {
#pragma unroll
        for (int q = 0; q < 16; q++) s += x[((c * 16 + a) * 16 + q) * 16 + b];
    }
    g_planes[idx] = s * (1.0f / 16.0f);
}

// ---------------------------------------------------------------------------
// Point sampling: 1 block = 1 point, 128 threads = channels.
// ---------------------------------------------------------------------------
__device__ __forceinline__ float bil_tap(const float* __restrict__ img,
                                         float gx, float gy, int c)
{
    float ix = (gx + 1.0f) * 0.5f * 15.0f;
    float iy = (gy + 1.0f) * 0.5f * 15.0f;
    float x0f = floorf(ix), y0f = floorf(iy);
    int   x0  = (int)x0f,   y0  = (int)y0f;
    float wx = ix - x0f, wy = iy - y0f;

    float acc = 0.0f;
#pragma unroll
    for (int j = 0; j < 2; j++) {
#pragma unroll
        for (int i = 0; i < 2; i++) {
            int xx = x0 + i, yy = y0 + j;
            float w = (j ? wy : 1.0f - wy) * (i ? wx : 1.0f - wx);
            bool valid = (unsigned)xx < 16u && (unsigned)yy < 16u;
            int xc = min(max(xx, 0), 15);
            int yc = min(max(yy, 0), 15);
            float v = img[(yc * 16 + xc) * 128 + c];
            acc += v * (valid ? w : 0.0f);
        }
    }
    return acc;
}

__global__ void sample_kernel(const float* __restrict__ coords,
                              float* __restrict__ out)
{
    const int p = blockIdx.x;
    const int c = threadIdx.x;
    const float cx = coords[p * 3 + 0];
    const float cy = coords[p * 3 + 1];
    const float cz = coords[p * 3 + 2];

    const int psz = 16 * 16 * 128;
    float acc = 0.0f;
    acc += bil_tap(g_planes + 0 * psz, cx, cy, c);   // p_xy
    acc += bil_tap(g_planes + 1 * psz, cy, cz, c);   // p_yz
    acc += bil_tap(g_planes + 2 * psz, cx, cz, c);   // p_xz

    out[p * 128 + c] = acc;
}

// ---------------------------------------------------------------------------
// Launch
// ---------------------------------------------------------------------------
extern "C" void kernel_launch(void* const* d_in, const int* in_sizes, int n_in,
                              void* d_out, int out_size)
{
    const float*         x      = (const float*)d_in[0];
    const void*          mask   = d_in[1];
    const float*         coords = (const float*)d_in[2];
    const float* w0a = (const float*)d_in[3];  const float* bn0a = (const float*)d_in[4];
    const float* w0b = (const float*)d_in[5];  const float* bn0b = (const float*)d_in[6];
    const float* wd0 = (const float*)d_in[7];  const float* bnd0 = (const float*)d_in[8];
    const float* w1a = (const float*)d_in[9];  const float* bn1a = (const float*)d_in[10];
    const float* w1b = (const float*)d_in[11]; const float* bn1b = (const float*)d_in[12];
    const float* wd1 = (const float*)d_in[13]; const float* bnd1 = (const float*)d_in[14];
    const float* w2a = (const float*)d_in[15]; const float* bn2a = (const float*)d_in[16];
    const float* w2b = (const float*)d_in[17]; const float* bn2b = (const float*)d_in[18];
    const float* w2c = (const float*)d_in[19]; const float* bn2c = (const float*)d_in[20];

    float *m0, *m1, *m2, *xm, *A, *B;
    cudaGetSymbolAddress((void**)&m0, g_m0);
    cudaGetSymbolAddress((void**)&m1, g_m1);
    cudaGetSymbolAddress((void**)&m2, g_m2);
    cudaGetSymbolAddress((void**)&xm, g_xm);
    cudaGetSymbolAddress((void**)&A,  g_bufA);
    cudaGetSymbolAddress((void**)&B,  g_bufB);

    // mask dtype detection + pyramid + masked input
    detect_mask_kernel<<<1, 256>>>((const unsigned int*)mask);
    prep_kernel<<<NV0 / 256, 256>>>(mask, x);
    downmask_kernel<<<NV1 / 256, 256>>>(m0, m1, 64);
    downmask_kernel<<<NV2 / 256, 256>>>(m1, m2, 32);

    // level 0 (64^3): 131072 voxel-pairs -> 512 x-blocks
    conv2_kernel<32,1><<<dim3(512, 1), 256>>>(xm, A, w0a, bn0a, m0, 16, 32, 64, 64);
    conv2_kernel<32,1><<<dim3(512, 1), 256>>>(A,  B, w0b, bn0b, m0, 32, 32, 64, 64);
    // downsample to 32^3: 64 x-blocks
    conv2_kernel<16,2><<<dim3(64, 2),  256>>>(B,  A, wd0, bnd0, m1, 32, 32, 64, 32);
    // level 1 (32^3)
    conv2_kernel<16,1><<<dim3(64, 4),  256>>>(A,  B, w1a, bn1a, m1, 32, 64, 32, 32);
    conv2_kernel<16,1><<<dim3(64, 4),  256>>>(B,  A, w1b, bn1b, m1, 64, 64, 32, 32);
    // downsample to 16^3: 8 x-blocks
    conv2_kernel<8,2><<<dim3(8, 16),   256>>>(A,  B, wd1, bnd1, m2, 64, 128, 32, 16);
    // level 2 (16^3)
    conv2_kernel<8,1><<<dim3(8, 16),   256>>>(B,  A, w2a, bn2a, m2, 128, 128, 16, 16);
    conv2_kernel<8,1><<<dim3(8, 16),   256>>>(A,  B, w2b, bn2b, m2, 128, 128, 16, 16);
    conv2_kernel<8,1><<<dim3(8, 16),   256>>>(B,  A, w2c, bn2c, m2, 128, 128, 16, 16);

    // projections + sampling
    proj_kernel<<<(3 * 16 * 16 * 128) / 128, 128>>>(A);
    int P = in_sizes[2] / 3;
    sample_kernel<<<P, 128>>>(coords, (float*)d_out);
}

// round 4
// speedup vs baseline: 1.9431x; 1.5477x over previous
#include <cuda_runtime.h>
#include <cstdint>

// ---------------------------------------------------------------------------
// SparseConvNet_Triplane: masked 3D CNN (64^3 -> 32^3 -> 16^3) + triplane
// projection + bilinear point sampling.
// R4: f32x2 conv, 4 voxels/thread (1 LDS.64 weight -> 4 FFMA2),
//     split-CI for the low-parallelism 16^3 layers.
// ---------------------------------------------------------------------------

#define NV0 (64*64*64)      // 262144
#define NV1 (32*32*32)      // 32768
#define NV2 (16*16*16)      // 4096

__device__ __align__(16) float g_m0[NV0];
__device__ __align__(16) float g_m1[NV1];
__device__ __align__(16) float g_m2[NV2];
__device__ __align__(16) float g_xm[16 * NV0];
__device__ __align__(16) float g_bufA[32 * NV0];
__device__ __align__(16) float g_bufB[32 * NV0];
__device__ __align__(16) float g_part[4 * 128 * NV2];   // split-CI partials
__device__ __align__(16) float g_planes[3 * 16 * 16 * 128];
__device__ int   g_mask_mode;

// ---------------------------------------------------------------------------
// f32x2 packed helpers
// ---------------------------------------------------------------------------
__device__ __forceinline__ unsigned long long ffma2(unsigned long long a,
                                                    unsigned long long b,
                                                    unsigned long long c)
{
    unsigned long long d;
    asm("fma.rn.f32x2 %0, %1, %2, %3;" : "=l"(d) : "l"(a), "l"(b), "l"(c));
    return d;
}
__device__ __forceinline__ unsigned long long bcast2(float v)
{
    unsigned long long d;
    asm("mov.b64 %0, {%1, %1};" : "=l"(d) : "f"(v));
    return d;
}
__device__ __forceinline__ float2 unpack2(unsigned long long a)
{
    float2 r;
    asm("mov.b64 {%0, %1}, %2;" : "=f"(r.x), "=f"(r.y) : "l"(a));
    return r;
}

// ---------------------------------------------------------------------------
// Mask dtype detection (byte / int32 / float32 storage of the bool input).
// ---------------------------------------------------------------------------
__global__ void detect_mask_kernel(const unsigned int* __restrict__ mw)
{
    __shared__ int s_int, s_flt;
    if (threadIdx.x == 0) { s_int = 1; s_flt = 1; }
    __syncthreads();
    for (int i = threadIdx.x; i < NV0 / 4; i += 256) {
        unsigned int w = mw[i];
        if (w != 0u && w != 1u)           s_int = 0;
        if (w != 0u && w != 0x3F800000u)  s_flt = 0;
    }
    __syncthreads();
    if (threadIdx.x == 0)
        g_mask_mode = s_int ? 1 : (s_flt ? 2 : 0);
}

__global__ void prep_kernel(const void* __restrict__ mb,
                            const float* __restrict__ x)
{
    int v = blockIdx.x * 256 + threadIdx.x;
    int mode = g_mask_mode;
    float m;
    if (mode == 1)      m = ((const int*)mb)[v]            ? 1.0f : 0.0f;
    else if (mode == 2) m = (((const float*)mb)[v] != 0.f) ? 1.0f : 0.0f;
    else                m = ((const unsigned char*)mb)[v]  ? 1.0f : 0.0f;
    g_m0[v] = m;
#pragma unroll
    for (int c = 0; c < 16; c++)
        g_xm[c * NV0 + v] = x[c * NV0 + v] * m;
}

__global__ void downmask_kernel(const float* __restrict__ mi,
                                float* __restrict__ mo, int Din)
{
    int Dout = Din >> 1;
    int v = blockIdx.x * blockDim.x + threadIdx.x;
    int wI = v % Dout;
    int t  = v / Dout;
    int hI = t % Dout;
    int dI = t / Dout;
    float s = 0.0f;
#pragma unroll
    for (int kd = 0; kd < 3; kd++) {
        int id = 2 * dI + kd - 1;
        if ((unsigned)id >= (unsigned)Din) continue;
#pragma unroll
        for (int kh = 0; kh < 3; kh++) {
            int ih = 2 * hI + kh - 1;
            if ((unsigned)ih >= (unsigned)Din) continue;
#pragma unroll
            for (int kw = 0; kw < 3; kw++) {
                int iw = 2 * wI + kw - 1;
                if ((unsigned)iw >= (unsigned)Din) continue;
                s = fmaxf(s, mi[(id * Din + ih) * Din + iw]);
            }
        }
    }
    mo[v] = s;
}

// ---------------------------------------------------------------------------
// Conv 3x3x3, f32x2 packed, 4 voxels/thread, 16 output channels (8 pairs).
// Each weight LDS.64 feeds 4 FFMA2 (one per voxel) -> fma-pipe bound.
// SPLIT: compute a CI-slice [z*CIS, (z+1)*CIS) and write raw partial sums;
// otherwise fused BN+ReLU+mask epilogue.
// Grid: (nOut/1024, CO/16, nsplit). 256 threads.
// ---------------------------------------------------------------------------
template<int S, bool SPLIT>
__global__ __launch_bounds__(256)
void conv4_kernel(
    const float* __restrict__ in, float* __restrict__ out,
    const float* __restrict__ w, const float* __restrict__ bn,
    const float* __restrict__ mask,
    int CI, int CIS, int CO, int Din, int Dout)
{
    constexpr int HP   = 8;              // channel pairs (CO_T = 16)
    constexpr int NVAL = S * 3 + 3;      // 6 (S=1) or 9 (S=2)

    __shared__ __align__(16) float ws[8 * 27 * 16];
    const unsigned long long* ws64 = (const unsigned long long*)ws;

    const int vox0   = (blockIdx.x * 256 + threadIdx.x) * 4;
    const int coBase = blockIdx.y * 16;
    const int ciBase = SPLIT ? blockIdx.z * CIS : 0;
    const int nOut   = Dout * Dout * Dout;
    const int vol    = Din * Din * Din;

    const int w0 = vox0 % Dout;          // multiple of 4
    int t        = vox0 / Dout;
    const int hI = t % Dout;
    const int dI = t / Dout;

    // row base offsets (col = w0*S), -1 if (kd,kh) row out of bounds
    int rowOff[9];
    {
        int q = 0;
#pragma unroll
        for (int kd = 0; kd < 3; kd++) {
            int id = dI * S + kd - 1;
            bool vd = (unsigned)id < (unsigned)Din;
#pragma unroll
            for (int kh = 0; kh < 3; kh++) {
                int ih = hI * S + kh - 1;
                bool ok = vd && ((unsigned)ih < (unsigned)Din);
                rowOff[q++] = ok ? ((id * Din + ih) * Din + w0 * S) : -1;
            }
        }
    }
    // column validity for the NVAL touched input columns (cols w0*S-1 .. +NVAL-2)
    bool colOk[NVAL];
#pragma unroll
    for (int i = 0; i < NVAL; i++) {
        int col = w0 * S - 1 + i;
        colOk[i] = (unsigned)col < (unsigned)Din;
    }

    unsigned long long acc[HP][4];
#pragma unroll
    for (int p = 0; p < HP; p++)
#pragma unroll
        for (int j = 0; j < 4; j++) acc[p][j] = 0ull;

    for (int c0 = 0; c0 < CIS; c0 += 8) {
        __syncthreads();
        // stage 8 x 27 x 16 weights: ws[((cl*27)+k)*16 + co]
        for (int i = threadIdx.x; i < 8 * 27 * 16; i += 256) {
            int co = i & 15;
            int r  = i >> 4;
            int k  = r % 27;
            int cl = r / 27;
            ws[i] = w[((size_t)(coBase + co) * CI + (ciBase + c0 + cl)) * 27 + k];
        }
        __syncthreads();

#pragma unroll 1
        for (int cl = 0; cl < 8; cl++) {
            const float* ip = in + (size_t)(ciBase + c0 + cl) * vol;
            const unsigned long long* wp = ws64 + cl * (27 * HP);

#pragma unroll
            for (int r = 0; r < 9; r++) {
                const int  ro = rowOff[r];
                const bool rv = (ro >= 0);

                unsigned long long pv[NVAL];
#pragma unroll
                for (int i = 0; i < NVAL; i++) {
                    float v = (rv && colOk[i]) ? __ldg(ip + ro + i - 1) : 0.0f;
                    pv[i] = bcast2(v);
                }

#pragma unroll
                for (int kw = 0; kw < 3; kw++) {
                    const unsigned long long* wk = wp + (r * 3 + kw) * HP;
#pragma unroll
                    for (int p = 0; p < HP; p++) {
                        const unsigned long long wpair = wk[p];
#pragma unroll
                        for (int j = 0; j < 4; j++)
                            acc[p][j] = ffma2(wpair, pv[S * j + kw], acc[p][j]);
                    }
                }
            }
        }
    }

    if (SPLIT) {
        float* po = out + (size_t)blockIdx.z * CO * nOut;
#pragma unroll
        for (int p = 0; p < HP; p++) {
            float2 a0 = unpack2(acc[p][0]);
            float2 a1 = unpack2(acc[p][1]);
            float2 a2 = unpack2(acc[p][2]);
            float2 a3 = unpack2(acc[p][3]);
            int cg0 = coBase + 2 * p;
            float4 o0 = make_float4(a0.x, a1.x, a2.x, a3.x);
            float4 o1 = make_float4(a0.y, a1.y, a2.y, a3.y);
            *(float4*)(po + (size_t)cg0 * nOut + vox0)       = o0;
            *(float4*)(po + (size_t)(cg0 + 1) * nOut + vox0) = o1;
        }
    } else {
        const float4 mv = *(const float4*)(mask + vox0);
#pragma unroll
        for (int p = 0; p < HP; p++) {
            float2 a0 = unpack2(acc[p][0]);
            float2 a1 = unpack2(acc[p][1]);
            float2 a2 = unpack2(acc[p][2]);
            float2 a3 = unpack2(acc[p][3]);
            int cg0 = coBase + 2 * p;
            int cg1 = cg0 + 1;

            float gg0 = __ldg(bn + cg0),        gg1 = __ldg(bn + cg1);
            float bb0 = __ldg(bn + CO + cg0),   bb1 = __ldg(bn + CO + cg1);
            float uu0 = __ldg(bn + 2*CO + cg0), uu1 = __ldg(bn + 2*CO + cg1);
            float vv0 = __ldg(bn + 3*CO + cg0), vv1 = __ldg(bn + 3*CO + cg1);
            float s0 = gg0 * rsqrtf(vv0 + 1e-3f);
            float s1 = gg1 * rsqrtf(vv1 + 1e-3f);

            float4 o0, o1;
            o0.x = fmaxf(fmaf(s0, a0.x - uu0, bb0), 0.0f) * mv.x;
            o0.y = fmaxf(fmaf(s0, a1.x - uu0, bb0), 0.0f) * mv.y;
            o0.z = fmaxf(fmaf(s0, a2.x - uu0, bb0), 0.0f) * mv.z;
            o0.w = fmaxf(fmaf(s0, a3.x - uu0, bb0), 0.0f) * mv.w;
            o1.x = fmaxf(fmaf(s1, a0.y - uu1, bb1), 0.0f) * mv.x;
            o1.y = fmaxf(fmaf(s1, a1.y - uu1, bb1), 0.0f) * mv.y;
            o1.z = fmaxf(fmaf(s1, a2.y - uu1, bb1), 0.0f) * mv.z;
            o1.w = fmaxf(fmaf(s1, a3.y - uu1, bb1), 0.0f) * mv.w;

            *(float4*)(out + (size_t)cg0 * nOut + vox0) = o0;
            *(float4*)(out + (size_t)cg1 * nOut + vox0) = o1;
        }
    }
}

// ---------------------------------------------------------------------------
// Reduce split-CI partials + BN + ReLU + mask.
// ---------------------------------------------------------------------------
__global__ void reduce_bn_kernel(const float* __restrict__ part,
                                 float* __restrict__ out,
                                 const float* __restrict__ bn,
                                 const float* __restrict__ mask,
                                 int CO, int nOut, int nsplit)
{
    int idx = blockIdx.x * 256 + threadIdx.x;       // CO * nOut total
    float s = 0.0f;
    for (int z = 0; z < nsplit; z++)
        s += part[(size_t)z * CO * nOut + idx];
    int c = idx / nOut;
    int v = idx - c * nOut;
    float g  = __ldg(bn + c);
    float b  = __ldg(bn + CO + c);
    float mu = __ldg(bn + 2 * CO + c);
    float vv = __ldg(bn + 3 * CO + c);
    float sc = g * rsqrtf(vv + 1e-3f);
    out[idx] = fmaxf(fmaf(sc, s - mu, b), 0.0f) * mask[v];
}

// ---------------------------------------------------------------------------
// Triplane projection: x [128][16][16][16] -> planes [3][16][16][128]
// ---------------------------------------------------------------------------
__global__ void proj_kernel(const float* __restrict__ x)
{
    int idx = blockIdx.x * 128 + threadIdx.x;
    int c = idx & 127;
    int r = idx >> 7;
    int b = r & 15;  r >>= 4;
    int a = r & 15;
    int p = r >> 4;

    float s = 0.0f;
    if (p == 0) {
#pragma unroll
        for (int d = 0; d < 16; d++) s += x[((c * 16 + d) * 16 + a) * 16 + b];
    } else if (p == 1) {
#pragma unroll
        for (int q = 0; q < 16; q++) s += x[((c * 16 + a) * 16 + b) * 16 + q];
    } else {
#pragma unroll
        for (int q = 0; q < 16; q++) s += x[((c * 16 + a) * 16 + q) * 16 + b];
    }
    g_planes[idx] = s * (1.0f / 16.0f);
}

// ---------------------------------------------------------------------------
// Point sampling: 1 block = 1 point, 128 threads = channels.
// ---------------------------------------------------------------------------
__device__ __forceinline__ float bil_tap(const float* __restrict__ img,
                                         float gx, float gy, int c)
{
    float ix = (gx + 1.0f) * 0.5f * 15.0f;
    float iy = (gy + 1.0f) * 0.5f * 15.0f;
    float x0f = floorf(ix), y0f = floorf(iy);
    int   x0  = (int)x0f,   y0  = (int)y0f;
    float wx = ix - x0f, wy = iy - y0f;

    float acc = 0.0f;
#pragma unroll
    for (int j = 0; j < 2; j++) {
#pragma unroll
        for (int i = 0; i < 2; i++) {
            int xx = x0 + i, yy = y0 + j;
            float w = (j ? wy : 1.0f - wy) * (i ? wx : 1.0f - wx);
            bool valid = (unsigned)xx < 16u && (unsigned)yy < 16u;
            int xc = min(max(xx, 0), 15);
            int yc = min(max(yy, 0), 15);
            float v = img[(yc * 16 + xc) * 128 + c];
            acc += v * (valid ? w : 0.0f);
        }
    }
    return acc;
}

__global__ void sample_kernel(const float* __restrict__ coords,
                              float* __restrict__ out)
{
    const int p = blockIdx.x;
    const int c = threadIdx.x;
    const float cx = coords[p * 3 + 0];
    const float cy = coords[p * 3 + 1];
    const float cz = coords[p * 3 + 2];

    const int psz = 16 * 16 * 128;
    float acc = 0.0f;
    acc += bil_tap(g_planes + 0 * psz, cx, cy, c);
    acc += bil_tap(g_planes + 1 * psz, cy, cz, c);
    acc += bil_tap(g_planes + 2 * psz, cx, cz, c);

    out[p * 128 + c] = acc;
}

// ---------------------------------------------------------------------------
// Launch
// ---------------------------------------------------------------------------
extern "C" void kernel_launch(void* const* d_in, const int* in_sizes, int n_in,
                              void* d_out, int out_size)
{
    const float* x      = (const float*)d_in[0];
    const void*  mask   = d_in[1];
    const float* coords = (const float*)d_in[2];
    const float* w0a = (const float*)d_in[3];  const float* bn0a = (const float*)d_in[4];
    const float* w0b = (const float*)d_in[5];  const float* bn0b = (const float*)d_in[6];
    const float* wd0 = (const float*)d_in[7];  const float* bnd0 = (const float*)d_in[8];
    const float* w1a = (const float*)d_in[9];  const float* bn1a = (const float*)d_in[10];
    const float* w1b = (const float*)d_in[11]; const float* bn1b = (const float*)d_in[12];
    const float* wd1 = (const float*)d_in[13]; const float* bnd1 = (const float*)d_in[14];
    const float* w2a = (const float*)d_in[15]; const float* bn2a = (const float*)d_in[16];
    const float* w2b = (const float*)d_in[17]; const float* bn2b = (const float*)d_in[18];
    const float* w2c = (const float*)d_in[19]; const float* bn2c = (const float*)d_in[20];

    float *m0, *m1, *m2, *xm, *A, *B, *P;
    cudaGetSymbolAddress((void**)&m0, g_m0);
    cudaGetSymbolAddress((void**)&m1, g_m1);
    cudaGetSymbolAddress((void**)&m2, g_m2);
    cudaGetSymbolAddress((void**)&xm, g_xm);
    cudaGetSymbolAddress((void**)&A,  g_bufA);
    cudaGetSymbolAddress((void**)&B,  g_bufB);
    cudaGetSymbolAddress((void**)&P,  g_part);

    detect_mask_kernel<<<1, 256>>>((const unsigned int*)mask);
    prep_kernel<<<NV0 / 256, 256>>>(mask, x);
    downmask_kernel<<<NV1 / 256, 256>>>(m0, m1, 64);
    downmask_kernel<<<NV2 / 256, 256>>>(m1, m2, 32);

    // level 0 (64^3, CO=32): 256 x-blocks x 2
    conv4_kernel<1,false><<<dim3(256, 2), 256>>>(xm, A, w0a, bn0a, m0, 16, 16, 32, 64, 64);
    conv4_kernel<1,false><<<dim3(256, 2), 256>>>(A,  B, w0b, bn0b, m0, 32, 32, 32, 64, 64);
    // downsample 64^3 -> 32^3 (CO=32)
    conv4_kernel<2,false><<<dim3(32, 2),  256>>>(B,  A, wd0, bnd0, m1, 32, 32, 32, 64, 32);
    // level 1 (32^3, CO=64)
    conv4_kernel<1,false><<<dim3(32, 4),  256>>>(A,  B, w1a, bn1a, m1, 32, 32, 64, 32, 32);
    conv4_kernel<1,false><<<dim3(32, 4),  256>>>(B,  A, w1b, bn1b, m1, 64, 64, 64, 32, 32);
    // downsample 32^3 -> 16^3 (CO=128), split CI=64 into 2
    conv4_kernel<2,true><<<dim3(4, 8, 2), 256>>>(A,  P, wd1, bnd1, m2, 64, 32, 128, 32, 16);
    reduce_bn_kernel<<<(128 * NV2) / 256, 256>>>(P, B, bnd1, m2, 128, NV2, 2);
    // level 2 (16^3, CO=128), split CI=128 into 4
    conv4_kernel<1,true><<<dim3(4, 8, 4), 256>>>(B,  P, w2a, bn2a, m2, 128, 32, 128, 16, 16);
    reduce_bn_kernel<<<(128 * NV2) / 256, 256>>>(P, A, bn2a, m2, 128, NV2, 4);
    conv4_kernel<1,true><<<dim3(4, 8, 4), 256>>>(A,  P, w2b, bn2b, m2, 128, 32, 128, 16, 16);
    reduce_bn_kernel<<<(128 * NV2) / 256, 256>>>(P, B, bn2b, m2, 128, NV2, 4);
    conv4_kernel<1,true><<<dim3(4, 8, 4), 256>>>(B,  P, w2c, bn2c, m2, 128, 32, 128, 16, 16);
    reduce_bn_kernel<<<(128 * NV2) / 256, 256>>>(P, A, bn2c, m2, 128, NV2, 4);

    // projections + sampling
    proj_kernel<<<(3 * 16 * 16 * 128) / 128, 128>>>(A);
    int Pn = in_sizes[2] / 3;
    sample_kernel<<<Pn, 128>>>(coords, (float*)d_out);
}